// round 1
// baseline (speedup 1.0000x reference)
#include <cuda_runtime.h>
#include <cstdint>

#define BATCH  16384
#define D      512
#define OUTD   2048
#define NLAYER 4

// Scratch (no allocations allowed)
__device__ float g_c[BATCH];            // per-row residual scalar for current layer
__device__ float g_wsum[NLAYER * D];    // rowsum of W: wsum[i*D+e] = sum_d W[i,e,d]

__device__ __forceinline__ float to_tf32(float x) {
    float y;
    asm("cvt.rna.tf32.f32 %0, %1;" : "=f"(y) : "f"(x));
    return y;
}

__device__ __forceinline__ void mma_tf32(float* c, const float* a, const float* b) {
    asm volatile(
        "mma.sync.aligned.m16n8k8.row.col.f32.tf32.tf32.f32 "
        "{%0,%1,%2,%3}, {%4,%5,%6,%7}, {%8,%9}, {%0,%1,%2,%3};\n"
        : "+f"(c[0]), "+f"(c[1]), "+f"(c[2]), "+f"(c[3])
        : "r"(__float_as_uint(a[0])), "r"(__float_as_uint(a[1])),
          "r"(__float_as_uint(a[2])), "r"(__float_as_uint(a[3])),
          "r"(__float_as_uint(b[0])), "r"(__float_as_uint(b[1])));
}

// ---------------------------------------------------------------------------
// wsum[i*D+e] = sum_d W[i,e,d]; one warp per output
// ---------------------------------------------------------------------------
__global__ void wsum_kernel(const float* __restrict__ W) {
    int warp = (blockIdx.x * blockDim.x + threadIdx.x) >> 5;
    int lane = threadIdx.x & 31;
    if (warp >= NLAYER * D) return;
    const float4* row = (const float4*)(W + (size_t)warp * D);
    float s = 0.f;
#pragma unroll
    for (int k = 0; k < 4; k++) {
        float4 v = row[lane + 32 * k];
        s += v.x + v.y + v.z + v.w;
    }
#pragma unroll
    for (int off = 16; off; off >>= 1) s += __shfl_xor_sync(0xffffffffu, s, off);
    if (lane == 0) g_wsum[warp] = s;
}

// ---------------------------------------------------------------------------
// Residual scalar: for layer `layer` (>=1), a_layer = out[:, (layer-1)*D : ...].
// c = 0; for j in 0..layer-1: c = c + dot(a_layer, a_j) + c * sum(a_j)
// One warp per row. All in fp32 (exact path).
// ---------------------------------------------------------------------------
__global__ void residual_kernel(const float* __restrict__ x,
                                const float* __restrict__ out,
                                int layer) {
    int row  = (blockIdx.x * blockDim.x + threadIdx.x) >> 5;
    int lane = threadIdx.x & 31;
    if (row >= BATCH) return;

    const float4* ai = (const float4*)(out + (size_t)row * OUTD + (size_t)(layer - 1) * D);
    float4 av[4];
#pragma unroll
    for (int k = 0; k < 4; k++) av[k] = ai[lane + 32 * k];

    float dots[3], sums[3];
    for (int j = 0; j < layer; j++) {
        const float4* aj = (j == 0)
            ? (const float4*)(x + (size_t)row * D)
            : (const float4*)(out + (size_t)row * OUTD + (size_t)(j - 1) * D);
        float dp = 0.f, sm = 0.f;
#pragma unroll
        for (int k = 0; k < 4; k++) {
            float4 b = aj[lane + 32 * k];
            dp += av[k].x * b.x + av[k].y * b.y + av[k].z * b.z + av[k].w * b.w;
            sm += b.x + b.y + b.z + b.w;
        }
#pragma unroll
        for (int off = 16; off; off >>= 1) {
            dp += __shfl_xor_sync(0xffffffffu, dp, off);
            sm += __shfl_xor_sync(0xffffffffu, sm, off);
        }
        dots[j] = dp; sums[j] = sm;
    }
    if (lane == 0) {
        float c = 0.f;
        for (int j = 0; j < layer; j++) c = c + dots[j] + c * sums[j];
        g_c[row] = c;
    }
}

// ---------------------------------------------------------------------------
// GEMM: out[r, e] = sum_d A[r,d] * Wl[e,d]  + c[r]*wsum[e] + bias[e]
// Tiles: 128x128x16, 256 threads (8 warps, 2x4 of 64x32), m16n8k8 tf32 mma.
// ---------------------------------------------------------------------------
#define BM 128
#define BN 128
#define BK 16
#define KTILES (D / BK)   // 32

__global__ __launch_bounds__(256, 2)
void gemm_kernel(const float* __restrict__ A, int lda,
                 const float* __restrict__ Wl,     // W + layer*D*D
                 const float* __restrict__ bias,   // b + layer*D
                 int wsum_off,                     // layer*D
                 int use_c,
                 float* __restrict__ out)          // d_out + layer*D, row stride OUTD
{
    __shared__ float As[2][BM][BK + 4];
    __shared__ float Bs[2][BN][BK + 4];

    int tid  = threadIdx.x;
    int warp = tid >> 5;
    int lane = tid & 31;
    int wm = (warp >> 2) * 64;    // 0 or 64
    int wn = (warp & 3) * 32;     // 0..96
    int g = lane >> 2;            // 0..7
    int t = lane & 3;             // 0..3

    int ldr = tid >> 2;           // 0..63
    int ldk = (tid & 3) * 4;      // 0,4,8,12

    const float* Ag = A  + (size_t)(blockIdx.y * BM + ldr) * lda + ldk;
    const float* Bg = Wl + (size_t)(blockIdx.x * BN + ldr) * D   + ldk;

    float acc[4][4][4];
#pragma unroll
    for (int i = 0; i < 4; i++)
#pragma unroll
        for (int j = 0; j < 4; j++)
#pragma unroll
            for (int k = 0; k < 4; k++) acc[i][j][k] = 0.f;

    // prologue: tile 0
    {
        float4 a0 = *(const float4*)(Ag);
        float4 a1 = *(const float4*)(Ag + (size_t)64 * lda);
        float4 b0 = *(const float4*)(Bg);
        float4 b1 = *(const float4*)(Bg + (size_t)64 * D);
        float4 ta0 = make_float4(to_tf32(a0.x), to_tf32(a0.y), to_tf32(a0.z), to_tf32(a0.w));
        float4 ta1 = make_float4(to_tf32(a1.x), to_tf32(a1.y), to_tf32(a1.z), to_tf32(a1.w));
        float4 tb0 = make_float4(to_tf32(b0.x), to_tf32(b0.y), to_tf32(b0.z), to_tf32(b0.w));
        float4 tb1 = make_float4(to_tf32(b1.x), to_tf32(b1.y), to_tf32(b1.z), to_tf32(b1.w));
        *(float4*)&As[0][ldr][ldk]      = ta0;
        *(float4*)&As[0][ldr + 64][ldk] = ta1;
        *(float4*)&Bs[0][ldr][ldk]      = tb0;
        *(float4*)&Bs[0][ldr + 64][ldk] = tb1;
    }
    __syncthreads();

    for (int kt = 0; kt < KTILES; kt++) {
        int s = kt & 1;
        float4 na0, na1, nb0, nb1;
        bool pf = (kt + 1 < KTILES);
        if (pf) {
            int ko = (kt + 1) * BK;
            na0 = *(const float4*)(Ag + ko);
            na1 = *(const float4*)(Ag + (size_t)64 * lda + ko);
            nb0 = *(const float4*)(Bg + ko);
            nb1 = *(const float4*)(Bg + (size_t)64 * D + ko);
        }

#pragma unroll
        for (int k0 = 0; k0 < BK; k0 += 8) {
            float afr[4][4];
#pragma unroll
            for (int mt = 0; mt < 4; mt++) {
                int rb = wm + mt * 16 + g;
                afr[mt][0] = As[s][rb][k0 + t];
                afr[mt][1] = As[s][rb + 8][k0 + t];
                afr[mt][2] = As[s][rb][k0 + t + 4];
                afr[mt][3] = As[s][rb + 8][k0 + t + 4];
            }
            float bfr[4][2];
#pragma unroll
            for (int nt = 0; nt < 4; nt++) {
                int cb = wn + nt * 8 + g;
                bfr[nt][0] = Bs[s][cb][k0 + t];
                bfr[nt][1] = Bs[s][cb][k0 + t + 4];
            }
#pragma unroll
            for (int mt = 0; mt < 4; mt++)
#pragma unroll
                for (int nt = 0; nt < 4; nt++)
                    mma_tf32(acc[mt][nt], afr[mt], bfr[nt]);
        }

        if (pf) {
            int ns = s ^ 1;
            *(float4*)&As[ns][ldr][ldk]      = make_float4(to_tf32(na0.x), to_tf32(na0.y), to_tf32(na0.z), to_tf32(na0.w));
            *(float4*)&As[ns][ldr + 64][ldk] = make_float4(to_tf32(na1.x), to_tf32(na1.y), to_tf32(na1.z), to_tf32(na1.w));
            *(float4*)&Bs[ns][ldr][ldk]      = make_float4(to_tf32(nb0.x), to_tf32(nb0.y), to_tf32(nb0.z), to_tf32(nb0.w));
            *(float4*)&Bs[ns][ldr + 64][ldk] = make_float4(to_tf32(nb1.x), to_tf32(nb1.y), to_tf32(nb1.z), to_tf32(nb1.w));
        }
        __syncthreads();
    }

    // Epilogue: y += c[row]*wsum[e] + bias[e]
    int rowB = blockIdx.y * BM;
    int colB = blockIdx.x * BN;
#pragma unroll
    for (int mt = 0; mt < 4; mt++) {
        int r0 = rowB + wm + mt * 16 + g;
        float c0 = use_c ? g_c[r0] : 0.f;
        float c1 = use_c ? g_c[r0 + 8] : 0.f;
#pragma unroll
        for (int nt = 0; nt < 4; nt++) {
            int col = colB + wn + nt * 8 + 2 * t;
            float w0 = g_wsum[wsum_off + col];
            float w1 = g_wsum[wsum_off + col + 1];
            float bb0 = bias[col];
            float bb1 = bias[col + 1];
            float2 v0 = make_float2(acc[mt][nt][0] + c0 * w0 + bb0,
                                    acc[mt][nt][1] + c0 * w1 + bb1);
            float2 v1 = make_float2(acc[mt][nt][2] + c1 * w0 + bb0,
                                    acc[mt][nt][3] + c1 * w1 + bb1);
            *(float2*)(out + (size_t)r0 * OUTD + col)       = v0;
            *(float2*)(out + (size_t)(r0 + 8) * OUTD + col) = v1;
        }
    }
}

// ---------------------------------------------------------------------------
extern "C" void kernel_launch(void* const* d_in, const int* in_sizes, int n_in,
                              void* d_out, int out_size) {
    const float* x = (const float*)d_in[0];
    const float* W = (const float*)d_in[1];
    const float* b = (const float*)d_in[2];
    float* out = (float*)d_out;

    wsum_kernel<<<NLAYER * D / 8, 256>>>(W);

    dim3 ggrid(D / BN, BATCH / BM);   // (4, 128)

    // Layer 0: no residual
    gemm_kernel<<<ggrid, 256>>>(x, D, W, b, 0, 0, out);

    for (int i = 1; i < NLAYER; i++) {
        residual_kernel<<<BATCH * 32 / 256, 256>>>(x, out, i);
        gemm_kernel<<<ggrid, 256>>>(out + (size_t)(i - 1) * D, OUTD,
                                    W + (size_t)i * D * D,
                                    b + (size_t)i * D,
                                    i * D, 1,
                                    out + (size_t)i * D);
    }
}

// round 2
// speedup vs baseline: 1.0538x; 1.0538x over previous
#include <cuda_runtime.h>
#include <cstdint>

#define BATCH  16384
#define D      512
#define OUTD   2048
#define NLAYER 4

__device__ float g_c[BATCH];
__device__ float g_wsum[NLAYER * D];

__device__ __forceinline__ float to_tf32(float x) {
    float y;
    asm("cvt.rna.tf32.f32 %0, %1;" : "=f"(y) : "f"(x));
    return y;
}

__device__ __forceinline__ void mma_tf32(float* c, const float* a, const float* b) {
    asm volatile(
        "mma.sync.aligned.m16n8k8.row.col.f32.tf32.tf32.f32 "
        "{%0,%1,%2,%3}, {%4,%5,%6,%7}, {%8,%9}, {%0,%1,%2,%3};\n"
        : "+f"(c[0]), "+f"(c[1]), "+f"(c[2]), "+f"(c[3])
        : "r"(__float_as_uint(a[0])), "r"(__float_as_uint(a[1])),
          "r"(__float_as_uint(a[2])), "r"(__float_as_uint(a[3])),
          "r"(__float_as_uint(b[0])), "r"(__float_as_uint(b[1])));
}

// ---------------------------------------------------------------------------
__global__ void wsum_kernel(const float* __restrict__ W) {
    int warp = (blockIdx.x * blockDim.x + threadIdx.x) >> 5;
    int lane = threadIdx.x & 31;
    if (warp >= NLAYER * D) return;
    const float4* row = (const float4*)(W + (size_t)warp * D);
    float s = 0.f;
#pragma unroll
    for (int k = 0; k < 4; k++) {
        float4 v = row[lane + 32 * k];
        s += v.x + v.y + v.z + v.w;
    }
#pragma unroll
    for (int off = 16; off; off >>= 1) s += __shfl_xor_sync(0xffffffffu, s, off);
    if (lane == 0) g_wsum[warp] = s;
}

// ---------------------------------------------------------------------------
__global__ void residual_kernel(const float* __restrict__ x,
                                const float* __restrict__ out,
                                int layer) {
    int row  = (blockIdx.x * blockDim.x + threadIdx.x) >> 5;
    int lane = threadIdx.x & 31;
    if (row >= BATCH) return;

    const float4* ai = (const float4*)(out + (size_t)row * OUTD + (size_t)(layer - 1) * D);
    float4 av[4];
#pragma unroll
    for (int k = 0; k < 4; k++) av[k] = ai[lane + 32 * k];

    float dots[3], sums[3];
    for (int j = 0; j < layer; j++) {
        const float4* aj = (j == 0)
            ? (const float4*)(x + (size_t)row * D)
            : (const float4*)(out + (size_t)row * OUTD + (size_t)(j - 1) * D);
        float dp = 0.f, sm = 0.f;
#pragma unroll
        for (int k = 0; k < 4; k++) {
            float4 b = aj[lane + 32 * k];
            dp += av[k].x * b.x + av[k].y * b.y + av[k].z * b.z + av[k].w * b.w;
            sm += b.x + b.y + b.z + b.w;
        }
#pragma unroll
        for (int off = 16; off; off >>= 1) {
            dp += __shfl_xor_sync(0xffffffffu, dp, off);
            sm += __shfl_xor_sync(0xffffffffu, sm, off);
        }
        dots[j] = dp; sums[j] = sm;
    }
    if (lane == 0) {
        float c = 0.f;
        for (int j = 0; j < layer; j++) c = c + dots[j] + c * sums[j];
        g_c[row] = c;
    }
}

// ---------------------------------------------------------------------------
// GEMM 128x128x16 tiles, fragment-ordered SMEM:
//   A: float4 cells, block b=(k0*8+mtg), cell = g*4 + (t ^ (g&3) ^ k0),
//      idx16 = b*33 + cell; float4 = (a0,a1,a2,a3) of the m16n8k8 fragment.
//   B: float2 cells, block b=(k0*16+ntg), same cell formula,
//      idx8 = b*33 + cell; float2 = (b0,b1).
// Mainloop: 1 LDS.128 per A-fragment, 1 LDS.64 per B-fragment, conflict-free.
// ---------------------------------------------------------------------------
#define BM 128
#define BN 128
#define BK 16
#define KTILES (D / BK)   // 32

#define A_ST_SZ (16 * 33)          // float4 units per stage = 528
#define B_ST_SZ (32 * 33)          // float2 units per stage = 1056

__global__ __launch_bounds__(256, 2)
void gemm_kernel(const float* __restrict__ A, int lda,
                 const float* __restrict__ Wl,
                 const float* __restrict__ bias,
                 int wsum_off,
                 int use_c,
                 float* __restrict__ out)
{
    __shared__ float4 As[2][A_ST_SZ];
    __shared__ float2 Bs[2][B_ST_SZ];

    int tid  = threadIdx.x;
    int warp = tid >> 5;
    int lane = tid & 31;
    int wm16 = (warp >> 2) * 4;   // A mtg base: 0 or 4
    int wn8  = (warp & 3) * 4;    // B ntg base: 0,4,8,12
    int g = lane >> 2;            // 0..7
    int t = lane & 3;             // 0..3
    int tx = t ^ (g & 3);         // swizzled t for LDS

    // ---- loader decomposition ----
    int ldr = tid >> 2;           // 0..63
    int q   = tid & 3;
    int ldk = q * 4;              // 0,4,8,12
    int k0s = q >> 1;             // which k8-chunk
    int khs = q & 1;              // which k4-half

    // A store addresses (scalar float offsets into As[s] viewed as float*)
    int m1 = ldr, m2 = ldr + 64;
    int mtg1 = m1 >> 4, g1 = m1 & 7, r81 = (m1 >> 3) & 1;
    int mtg2 = m2 >> 4, g2 = m2 & 7, r82 = (m2 >> 3) & 1;
    int xa1 = (g1 & 3) ^ k0s;
    int xa2 = (g2 & 3) ^ k0s;
    int baseA1 = ((k0s * 8 + mtg1) * 33 + g1 * 4) * 4 + khs * 2 + r81;
    int baseA2 = ((k0s * 8 + mtg2) * 33 + g2 * 4) * 4 + khs * 2 + r82;

    // B store addresses (scalar float offsets into Bs[s] viewed as float*)
    int n1 = ldr, n2 = ldr + 64;
    int ntg1 = n1 >> 3, gb1 = n1 & 7;
    int ntg2 = n2 >> 3, gb2 = n2 & 7;
    int xb1 = (gb1 & 3) ^ k0s;
    int xb2 = (gb2 & 3) ^ k0s;
    int baseB1 = ((k0s * 16 + ntg1) * 33 + gb1 * 4) * 2 + khs;
    int baseB2 = ((k0s * 16 + ntg2) * 33 + gb2 * 4) * 2 + khs;

    const float* Ag = A  + (size_t)(blockIdx.y * BM + ldr) * lda + ldk;
    const float* Bg = Wl + (size_t)(blockIdx.x * BN + ldr) * D   + ldk;

    float acc[4][4][4];
#pragma unroll
    for (int i = 0; i < 4; i++)
#pragma unroll
        for (int j = 0; j < 4; j++)
#pragma unroll
            for (int k = 0; k < 4; k++) acc[i][j][k] = 0.f;

    // ---- store helper (macro to keep everything unrolled) ----
#define STORE_TILE(s, a0v, a1v, b0v, b1v)                                        \
    {                                                                            \
        float* Af = (float*)As[s];                                               \
        float* Bf = (float*)Bs[s];                                               \
        const float av0[4] = {a0v.x, a0v.y, a0v.z, a0v.w};                       \
        const float av1[4] = {a1v.x, a1v.y, a1v.z, a1v.w};                       \
        const float bv0[4] = {b0v.x, b0v.y, b0v.z, b0v.w};                       \
        const float bv1[4] = {b1v.x, b1v.y, b1v.z, b1v.w};                       \
        _Pragma("unroll")                                                        \
        for (int j = 0; j < 4; j++) {                                            \
            Af[baseA1 + ((j ^ xa1) << 2)] = to_tf32(av0[j]);                     \
            Af[baseA2 + ((j ^ xa2) << 2)] = to_tf32(av1[j]);                     \
            Bf[baseB1 + ((j ^ xb1) << 1)] = to_tf32(bv0[j]);                     \
            Bf[baseB2 + ((j ^ xb2) << 1)] = to_tf32(bv1[j]);                     \
        }                                                                        \
    }

    // prologue
    {
        float4 a0 = *(const float4*)(Ag);
        float4 a1 = *(const float4*)(Ag + (size_t)64 * lda);
        float4 b0 = *(const float4*)(Bg);
        float4 b1 = *(const float4*)(Bg + (size_t)64 * D);
        STORE_TILE(0, a0, a1, b0, b1);
    }
    __syncthreads();

    for (int kt = 0; kt < KTILES; kt++) {
        int s = kt & 1;
        float4 na0, na1, nb0, nb1;
        bool pf = (kt + 1 < KTILES);
        if (pf) {
            int ko = (kt + 1) * BK;
            na0 = *(const float4*)(Ag + ko);
            na1 = *(const float4*)(Ag + (size_t)64 * lda + ko);
            nb0 = *(const float4*)(Bg + ko);
            nb1 = *(const float4*)(Bg + (size_t)64 * D + ko);
        }

#pragma unroll
        for (int k0 = 0; k0 < 2; k0++) {
            int cell = g * 4 + (tx ^ k0);
            float4 afr[4];
            float2 bfr[4];
#pragma unroll
            for (int mt = 0; mt < 4; mt++)
                afr[mt] = As[s][(k0 * 8 + wm16 + mt) * 33 + cell];
#pragma unroll
            for (int nt = 0; nt < 4; nt++)
                bfr[nt] = Bs[s][(k0 * 16 + wn8 + nt) * 33 + cell];
#pragma unroll
            for (int mt = 0; mt < 4; mt++)
#pragma unroll
                for (int nt = 0; nt < 4; nt++)
                    mma_tf32(acc[mt][nt], (const float*)&afr[mt], (const float*)&bfr[nt]);
        }

        if (pf) {
            int ns = s ^ 1;
            STORE_TILE(ns, na0, na1, nb0, nb1);
        }
        __syncthreads();
    }

    // Epilogue: y += c[row]*wsum[e] + bias[e]
    int rowB = blockIdx.y * BM;
    int colB = blockIdx.x * BN;
    int wm = wm16 * 16;
    int wn = wn8 * 8;
#pragma unroll
    for (int mt = 0; mt < 4; mt++) {
        int r0 = rowB + wm + mt * 16 + g;
        float c0 = use_c ? g_c[r0] : 0.f;
        float c1 = use_c ? g_c[r0 + 8] : 0.f;
#pragma unroll
        for (int nt = 0; nt < 4; nt++) {
            int col = colB + wn + nt * 8 + 2 * t;
            float w0 = g_wsum[wsum_off + col];
            float w1 = g_wsum[wsum_off + col + 1];
            float bb0 = bias[col];
            float bb1 = bias[col + 1];
            float2 v0 = make_float2(acc[mt][nt][0] + c0 * w0 + bb0,
                                    acc[mt][nt][1] + c0 * w1 + bb1);
            float2 v1 = make_float2(acc[mt][nt][2] + c1 * w0 + bb0,
                                    acc[mt][nt][3] + c1 * w1 + bb1);
            *(float2*)(out + (size_t)r0 * OUTD + col)       = v0;
            *(float2*)(out + (size_t)(r0 + 8) * OUTD + col) = v1;
        }
    }
}

// ---------------------------------------------------------------------------
extern "C" void kernel_launch(void* const* d_in, const int* in_sizes, int n_in,
                              void* d_out, int out_size) {
    const float* x = (const float*)d_in[0];
    const float* W = (const float*)d_in[1];
    const float* b = (const float*)d_in[2];
    float* out = (float*)d_out;

    wsum_kernel<<<NLAYER * D / 8, 256>>>(W);

    dim3 ggrid(D / BN, BATCH / BM);   // (4, 128)

    gemm_kernel<<<ggrid, 256>>>(x, D, W, b, 0, 0, out);

    for (int i = 1; i < NLAYER; i++) {
        residual_kernel<<<BATCH * 32 / 256, 256>>>(x, out, i);
        gemm_kernel<<<ggrid, 256>>>(out + (size_t)(i - 1) * D, OUTD,
                                    W + (size_t)i * D * D,
                                    b + (size_t)i * D,
                                    i * D, 1,
                                    out + (size_t)i * D);
    }
}

// round 4
// speedup vs baseline: 1.9246x; 1.8264x over previous
#include <cuda_runtime.h>
#include <cuda_fp16.h>
#include <cstdint>

#define BATCH  16384
#define D      512
#define OUTD   2048
#define NLAYER 4

#define BM 128
#define BN 128
#define BKH 32                         // halves per k-tile (64B rows)
#define NTILES (D / BKH)               // 16
#define NSTAGE 4
#define STAGE_BYTES (BM * 64 + BN * 64)  // 16384 (A 8KB + B 8KB)
#define SMEM_MAIN (NSTAGE * STAGE_BYTES) // 65536
#define SMEM_TOTAL (SMEM_MAIN + 1024)

__device__ float  g_c[BATCH];
__device__ float  g_wsum[NLAYER * D];
__device__ __half g_h0[(size_t)BATCH * D];
__device__ __half g_h1[(size_t)BATCH * D];
__device__ __half g_wh[(size_t)NLAYER * D * D];

// ---------------- helpers ----------------
__device__ __forceinline__ uint32_t s2u(const void* p) {
    uint32_t a;
    asm("{ .reg .u64 t; cvta.to.shared.u64 t, %1; cvt.u32.u64 %0, t; }" : "=r"(a) : "l"(p));
    return a;
}
__device__ __forceinline__ uint64_t g2g(const void* p) {
    uint64_t a;
    asm("cvta.to.global.u64 %0, %1;" : "=l"(a) : "l"(p));
    return a;
}
__device__ __forceinline__ void cp16(uint32_t s, uint64_t g) {
    asm volatile("cp.async.cg.shared.global [%0], [%1], 16;" :: "r"(s), "l"(g) : "memory");
}
#define CP_COMMIT() asm volatile("cp.async.commit_group;" ::: "memory")
#define CP_WAIT2()  asm volatile("cp.async.wait_group 2;" ::: "memory")

__device__ __forceinline__ void ldsm4(uint32_t& r0, uint32_t& r1, uint32_t& r2, uint32_t& r3,
                                      uint32_t addr) {
    asm volatile("ldmatrix.sync.aligned.m8n8.x4.shared.b16 {%0,%1,%2,%3}, [%4];"
                 : "=r"(r0), "=r"(r1), "=r"(r2), "=r"(r3) : "r"(addr));
}
__device__ __forceinline__ void mma_f16(float* c, const uint32_t* a, const uint32_t* b) {
    asm volatile(
        "mma.sync.aligned.m16n8k16.row.col.f32.f16.f16.f32 "
        "{%0,%1,%2,%3}, {%4,%5,%6,%7}, {%8,%9}, {%0,%1,%2,%3};\n"
        : "+f"(c[0]), "+f"(c[1]), "+f"(c[2]), "+f"(c[3])
        : "r"(a[0]), "r"(a[1]), "r"(a[2]), "r"(a[3]), "r"(b[0]), "r"(b[1]));
}

// ---------------- prep: W -> fp16 + wsum ----------------
__global__ void prep_w(const float* __restrict__ W) {
    int warp = (blockIdx.x * blockDim.x + threadIdx.x) >> 5;  // row of [2048 x 512]
    int lane = threadIdx.x & 31;
    if (warp >= NLAYER * D) return;
    const float4* row = (const float4*)(W + (size_t)warp * D);
    __half* hrow = g_wh + (size_t)warp * D;
    float s = 0.f;
#pragma unroll
    for (int k = 0; k < 4; k++) {
        int i4 = lane + 32 * k;
        float4 v = row[i4];
        s += v.x + v.y + v.z + v.w;
        __half2 h01 = __floats2half2_rn(v.x, v.y);
        __half2 h23 = __floats2half2_rn(v.z, v.w);
        uint2 pk = make_uint2(*(uint32_t*)&h01, *(uint32_t*)&h23);
        *(uint2*)(hrow + i4 * 4) = pk;
    }
#pragma unroll
    for (int off = 16; off; off >>= 1) s += __shfl_xor_sync(0xffffffffu, s, off);
    if (lane == 0) g_wsum[warp] = s;
}

// ---------------- prep: x -> fp16 (into g_h0) ----------------
__global__ void conv_x(const float* __restrict__ x) {
    size_t i = (size_t)blockIdx.x * blockDim.x + threadIdx.x;   // one float4 each
    float4 v = ((const float4*)x)[i];
    __half2 h01 = __floats2half2_rn(v.x, v.y);
    __half2 h23 = __floats2half2_rn(v.z, v.w);
    uint2 pk = make_uint2(*(uint32_t*)&h01, *(uint32_t*)&h23);
    *(uint2*)(g_h0 + i * 4) = pk;
}

// ---------------- residual scalar (exact fp32 path) ----------------
__global__ void residual_kernel(const float* __restrict__ x,
                                const float* __restrict__ out,
                                int layer) {
    int row  = (blockIdx.x * blockDim.x + threadIdx.x) >> 5;
    int lane = threadIdx.x & 31;
    if (row >= BATCH) return;

    const float4* ai = (const float4*)(out + (size_t)row * OUTD + (size_t)(layer - 1) * D);
    float4 av[4];
#pragma unroll
    for (int k = 0; k < 4; k++) av[k] = ai[lane + 32 * k];

    float dots[3], sums[3];
    for (int j = 0; j < layer; j++) {
        const float4* aj = (j == 0)
            ? (const float4*)(x + (size_t)row * D)
            : (const float4*)(out + (size_t)row * OUTD + (size_t)(j - 1) * D);
        float dp = 0.f, sm = 0.f;
#pragma unroll
        for (int k = 0; k < 4; k++) {
            float4 b = aj[lane + 32 * k];
            dp += av[k].x * b.x + av[k].y * b.y + av[k].z * b.z + av[k].w * b.w;
            sm += b.x + b.y + b.z + b.w;
        }
#pragma unroll
        for (int off = 16; off; off >>= 1) {
            dp += __shfl_xor_sync(0xffffffffu, dp, off);
            sm += __shfl_xor_sync(0xffffffffu, sm, off);
        }
        dots[j] = dp; sums[j] = sm;
    }
    if (lane == 0) {
        float c = 0.f;
        for (int j = 0; j < layer; j++) c = c + dots[j] + c * sums[j];
        g_c[row] = c;
    }
}

// ---------------- fp16 GEMM with cp.async + ldmatrix ----------------
// out[r,e] = sum_d A[r,d]*W[e,d] + c[r]*wsum[e] + bias[e]; also fp16 copy -> next buffer
__global__ __launch_bounds__(256, 2)
void gemm_h(int layer, int asel, int write_ah,
            const float* __restrict__ bias_all,
            float* __restrict__ out_base)
{
    extern __shared__ __align__(128) char dsm[];
    uint32_t sb = s2u(dsm);
    float* wsum_s = (float*)(dsm + SMEM_MAIN);
    float* bias_s = (float*)(dsm + SMEM_MAIN + 512);

    const __half* Ah = asel ? g_h1 : g_h0;
    __half*       Oh = asel ? g_h0 : g_h1;
    const __half* Wl = g_wh + (size_t)layer * D * D;
    const float*  bias = bias_all + layer * D;
    float* out = out_base + layer * D;
    int use_c = (layer > 0);

    int tid = threadIdx.x, warp = tid >> 5, lane = tid & 31;
    int rowB = blockIdx.y * BM, colB = blockIdx.x * BN;

    if (tid < 128) {
        wsum_s[tid] = g_wsum[layer * D + colB + tid];
        bias_s[tid] = bias[colB + tid];
    }

    // ---- loader setup: each thread 4 x cp.async.16B per tile ----
    int u = tid & 3, r = tid >> 2;                     // r: 0..63
    uint32_t swz = (uint32_t)((u ^ ((r >> 1) & 3)) << 4);
    uint32_t sA0 = sb + r * 64 + swz;
    uint32_t sB0 = sb + BM * 64 + r * 64 + swz;
    uint64_t gA = g2g(Ah + (size_t)(rowB + r) * D + u * 8);
    uint64_t gB = g2g(Wl + (size_t)(colB + r) * D + u * 8);

#define LOAD_TILE(kt, st)                                                 \
    {                                                                     \
        uint32_t so = (uint32_t)(st) * STAGE_BYTES;                       \
        uint64_t go = (uint64_t)(kt) * 64;                                \
        cp16(sA0 + so,        gA + go);                                   \
        cp16(sA0 + so + 4096, gA + go + 65536);                           \
        cp16(sB0 + so,        gB + go);                                   \
        cp16(sB0 + so + 4096, gB + go + 65536);                           \
    }

    // ---- fragment address setup ----
    int wm = (warp >> 2) * 64;          // 0 / 64
    int wn = (warp & 3) * 32;           // 0..96
    int xa = ((lane & 15) >> 1) & 3;
    int rb = (lane & 7) + ((lane >> 4) << 3);
    int xb = (rb >> 1) & 3;
    int ahc = lane >> 4;                // A k-half select
    int bhc = (lane >> 3) & 1;          // B k-half select
    uint32_t aRow = sb + (uint32_t)(wm + (lane & 15)) * 64;
    uint32_t bRow = sb + BM * 64 + (uint32_t)(wn + rb) * 64;

    float acc[4][4][4];
#pragma unroll
    for (int i = 0; i < 4; i++)
#pragma unroll
        for (int j = 0; j < 4; j++)
#pragma unroll
            for (int k = 0; k < 4; k++) acc[i][j][k] = 0.f;

    LOAD_TILE(0, 0); CP_COMMIT();
    LOAD_TILE(1, 1); CP_COMMIT();
    LOAD_TILE(2, 2); CP_COMMIT();

    for (int kt = 0; kt < NTILES; kt++) {
        CP_WAIT2();
        __syncthreads();
        if (kt + 3 < NTILES) LOAD_TILE(kt + 3, (kt + 3) & 3);
        CP_COMMIT();

        uint32_t so = (uint32_t)(kt & 3) * STAGE_BYTES;
#pragma unroll
        for (int s16 = 0; s16 < 2; s16++) {
            uint32_t afr[4][4];
            uint32_t bfr[2][4];
            uint32_t ca = (uint32_t)(((2 * s16 + ahc) ^ xa) << 4);
            uint32_t cb = (uint32_t)(((2 * s16 + bhc) ^ xb) << 4);
#pragma unroll
            for (int mt = 0; mt < 4; mt++)
                ldsm4(afr[mt][0], afr[mt][1], afr[mt][2], afr[mt][3],
                      aRow + so + (uint32_t)mt * 1024 + ca);
#pragma unroll
            for (int nb = 0; nb < 2; nb++)
                ldsm4(bfr[nb][0], bfr[nb][1], bfr[nb][2], bfr[nb][3],
                      bRow + so + (uint32_t)nb * 1024 + cb);
#pragma unroll
            for (int mt = 0; mt < 4; mt++)
#pragma unroll
                for (int nt = 0; nt < 4; nt++) {
                    uint32_t bpair[2] = { bfr[nt >> 1][(nt & 1) * 2],
                                          bfr[nt >> 1][(nt & 1) * 2 + 1] };
                    mma_f16(acc[mt][nt], afr[mt], bpair);
                }
        }
    }

    // ---- epilogue ----
    int g = lane >> 2, t = lane & 3;
#pragma unroll
    for (int mt = 0; mt < 4; mt++) {
        int m0 = rowB + wm + mt * 16 + g;
        float c0 = use_c ? g_c[m0] : 0.f;
        float c1 = use_c ? g_c[m0 + 8] : 0.f;
        float* o0 = out + (size_t)m0 * OUTD + colB;
        float* o1 = o0 + (size_t)8 * OUTD;
        __half* h0 = Oh + (size_t)m0 * D + colB;
        __half* h1 = h0 + (size_t)8 * D;
#pragma unroll
        for (int nt = 0; nt < 4; nt++) {
            int col = wn + nt * 8 + 2 * t;
            float w0 = wsum_s[col], w1 = wsum_s[col + 1];
            float bb0 = bias_s[col], bb1 = bias_s[col + 1];
            float v00 = acc[mt][nt][0] + c0 * w0 + bb0;
            float v01 = acc[mt][nt][1] + c0 * w1 + bb1;
            float v10 = acc[mt][nt][2] + c1 * w0 + bb0;
            float v11 = acc[mt][nt][3] + c1 * w1 + bb1;
            *(float2*)(o0 + col) = make_float2(v00, v01);
            *(float2*)(o1 + col) = make_float2(v10, v11);
            if (write_ah) {
                __half2 p0 = __floats2half2_rn(v00, v01);
                __half2 p1 = __floats2half2_rn(v10, v11);
                *(__half2*)(h0 + col) = p0;
                *(__half2*)(h1 + col) = p1;
            }
        }
    }
}

// ---------------------------------------------------------------------------
extern "C" void kernel_launch(void* const* d_in, const int* in_sizes, int n_in,
                              void* d_out, int out_size) {
    const float* x = (const float*)d_in[0];
    const float* W = (const float*)d_in[1];
    const float* b = (const float*)d_in[2];
    float* out = (float*)d_out;

    cudaFuncSetAttribute(gemm_h, cudaFuncAttributeMaxDynamicSharedMemorySize, SMEM_TOTAL);

    prep_w<<<NLAYER * D / 8, 256>>>(W);
    conv_x<<<(BATCH * D / 4) / 256, 256>>>(x);

    dim3 ggrid(D / BN, BATCH / BM);   // (4, 128)

    gemm_h<<<ggrid, 256, SMEM_TOTAL>>>(0, 0, 1, b, out);

    for (int i = 1; i < NLAYER; i++) {
        residual_kernel<<<BATCH * 32 / 256, 256>>>(x, out, i);
        gemm_h<<<ggrid, 256, SMEM_TOTAL>>>(i, i & 1, (i < NLAYER - 1) ? 1 : 0, b, out);
    }
}

// round 5
// speedup vs baseline: 1.9692x; 1.0232x over previous
#include <cuda_runtime.h>
#include <cuda_fp16.h>
#include <cstdint>

#define BATCH  16384
#define D      512
#define OUTD   2048
#define NLAYER 4

#define BM 128
#define BN 128
#define NTILES 16
#define STAGE_BYTES (BM * 64 + BN * 64)   // 16384
#define SMEM_MAIN (4 * STAGE_BYTES)       // 65536
#define SMEM_TOTAL (SMEM_MAIN + 1536)

__device__ float  g_wsum[NLAYER * D];
__device__ float  g_dot[3][3][BATCH];     // g_dot[i-1][j][row] = dot(a_i, a_j)
__device__ float  g_sum[3][BATCH];        // g_sum[j][row] = sum(a_j), a_0 = x
__device__ __half g_h0[(size_t)BATCH * D];
__device__ __half g_h1[(size_t)BATCH * D];
__device__ __half g_wh[(size_t)NLAYER * D * D];

// ---------------- helpers ----------------
__device__ __forceinline__ uint32_t s2u(const void* p) {
    uint32_t a;
    asm("{ .reg .u64 t; cvta.to.shared.u64 t, %1; cvt.u32.u64 %0, t; }" : "=r"(a) : "l"(p));
    return a;
}
__device__ __forceinline__ uint64_t g2g(const void* p) {
    uint64_t a;
    asm("cvta.to.global.u64 %0, %1;" : "=l"(a) : "l"(p));
    return a;
}
__device__ __forceinline__ void cp16(uint32_t s, uint64_t g) {
    asm volatile("cp.async.cg.shared.global [%0], [%1], 16;" :: "r"(s), "l"(g) : "memory");
}
#define CP_COMMIT() asm volatile("cp.async.commit_group;" ::: "memory")
#define CP_WAIT2()  asm volatile("cp.async.wait_group 2;" ::: "memory")

__device__ __forceinline__ void ldsm4(uint32_t& r0, uint32_t& r1, uint32_t& r2, uint32_t& r3,
                                      uint32_t addr) {
    asm volatile("ldmatrix.sync.aligned.m8n8.x4.shared.b16 {%0,%1,%2,%3}, [%4];"
                 : "=r"(r0), "=r"(r1), "=r"(r2), "=r"(r3) : "r"(addr));
}
__device__ __forceinline__ void mma_f16(float* c, const uint32_t* a, const uint32_t* b) {
    asm volatile(
        "mma.sync.aligned.m16n8k16.row.col.f32.f16.f16.f32 "
        "{%0,%1,%2,%3}, {%4,%5,%6,%7}, {%8,%9}, {%0,%1,%2,%3};\n"
        : "+f"(c[0]), "+f"(c[1]), "+f"(c[2]), "+f"(c[3])
        : "r"(a[0]), "r"(a[1]), "r"(a[2]), "r"(a[3]), "r"(b[0]), "r"(b[1]));
}

// ---------------- zero accumulators (graph-replay safe) ----------------
__global__ void zero_aux() {
    int i = blockIdx.x * blockDim.x + threadIdx.x;
    if (i < 9 * BATCH) ((float*)g_dot)[i] = 0.f;
    if (i < 3 * BATCH) ((float*)g_sum)[i] = 0.f;
}

// ---------------- prep: W -> fp16 + wsum ----------------
__global__ void prep_w(const float* __restrict__ W) {
    int warp = (blockIdx.x * blockDim.x + threadIdx.x) >> 5;
    int lane = threadIdx.x & 31;
    if (warp >= NLAYER * D) return;
    const float4* row = (const float4*)(W + (size_t)warp * D);
    __half* hrow = g_wh + (size_t)warp * D;
    float s = 0.f;
#pragma unroll
    for (int k = 0; k < 4; k++) {
        int i4 = lane + 32 * k;
        float4 v = row[i4];
        s += v.x + v.y + v.z + v.w;
        __half2 h01 = __floats2half2_rn(v.x, v.y);
        __half2 h23 = __floats2half2_rn(v.z, v.w);
        uint2 pk = make_uint2(*(uint32_t*)&h01, *(uint32_t*)&h23);
        *(uint2*)(hrow + i4 * 4) = pk;
    }
#pragma unroll
    for (int off = 16; off; off >>= 1) s += __shfl_xor_sync(0xffffffffu, s, off);
    if (lane == 0) g_wsum[warp] = s;
}

// ---------------- prep: x -> fp16 + row sums (one warp per row) ----------------
__global__ void conv_x(const float* __restrict__ x) {
    int row  = (blockIdx.x * blockDim.x + threadIdx.x) >> 5;
    int lane = threadIdx.x & 31;
    const float4* rp = (const float4*)(x + (size_t)row * D);
    __half* hp = g_h0 + (size_t)row * D;
    float s = 0.f;
#pragma unroll
    for (int k = 0; k < 4; k++) {
        int i4 = lane + 32 * k;
        float4 v = rp[i4];
        s += v.x + v.y + v.z + v.w;
        __half2 h01 = __floats2half2_rn(v.x, v.y);
        __half2 h23 = __floats2half2_rn(v.z, v.w);
        uint2 pk = make_uint2(*(uint32_t*)&h01, *(uint32_t*)&h23);
        *(uint2*)(hp + i4 * 4) = pk;
    }
#pragma unroll
    for (int off = 16; off; off >>= 1) s += __shfl_xor_sync(0xffffffffu, s, off);
    if (lane == 0) g_sum[0][row] = s;
}

// ---------------- fused fp16 GEMM ----------------
// Layer L: out = A @ W_L^T + c*wsum + bias, plus epilogue residual reductions
// for the NEXT layer: g_dot[L][j][row] += dot-partials, g_sum[L+1][row] (L<=1).
__global__ __launch_bounds__(256, 2)
void gemm_h(int layer, int asel, int write_ah,
            const float* __restrict__ x,
            const float* __restrict__ bias_all,
            float* __restrict__ out_base)
{
    extern __shared__ __align__(128) char dsm[];
    uint32_t sb = s2u(dsm);
    float* wsum_s = (float*)(dsm + SMEM_MAIN);
    float* bias_s = (float*)(dsm + SMEM_MAIN + 512);
    float* c_s    = (float*)(dsm + SMEM_MAIN + 1024);

    const __half* Ah = asel ? g_h1 : g_h0;
    __half*       Oh = asel ? g_h0 : g_h1;
    const __half* Wl = g_wh + (size_t)layer * D * D;
    float* out = out_base + layer * D;

    int tid = threadIdx.x, warp = tid >> 5, lane = tid & 31;
    int rowB = blockIdx.y * BM, colB = blockIdx.x * BN;

    int ndots = (layer < 3) ? (layer + 1) : 0;   // dots for a_{layer+1} vs a_0..a_layer
    int dosum = (layer <= 1);

    if (tid < 128) {
        wsum_s[tid] = g_wsum[layer * D + colB + tid];
        bias_s[tid] = bias_all[layer * D + colB + tid];
        float c = 0.f;
        if (layer > 0) {
            int row = rowB + tid;
#pragma unroll
            for (int j = 0; j < 3; j++)
                if (j < layer)
                    c = c + g_dot[layer - 1][j][row] + c * g_sum[j][row];
        }
        c_s[tid] = c;
    }

    // ---- loader ----
    int u = tid & 3, r = tid >> 2;
    uint32_t swz = (uint32_t)((u ^ ((r >> 1) & 3)) << 4);
    uint32_t sA0 = sb + r * 64 + swz;
    uint32_t sB0 = sb + BM * 64 + r * 64 + swz;
    uint64_t gA = g2g(Ah + (size_t)(rowB + r) * D + u * 8);
    uint64_t gB = g2g(Wl + (size_t)(colB + r) * D + u * 8);

#define LOAD_TILE(kt, st)                                                 \
    {                                                                     \
        uint32_t so = (uint32_t)(st) * STAGE_BYTES;                       \
        uint64_t go = (uint64_t)(kt) * 64;                                \
        cp16(sA0 + so,        gA + go);                                   \
        cp16(sA0 + so + 4096, gA + go + 65536);                           \
        cp16(sB0 + so,        gB + go);                                   \
        cp16(sB0 + so + 4096, gB + go + 65536);                           \
    }

    int wm = (warp >> 2) * 64;
    int wn = (warp & 3) * 32;
    int xa = ((lane & 15) >> 1) & 3;
    int rb = (lane & 7) + ((lane >> 4) << 3);
    int xb = (rb >> 1) & 3;
    int ahc = lane >> 4;
    int bhc = (lane >> 3) & 1;
    uint32_t aRow = sb + (uint32_t)(wm + (lane & 15)) * 64;
    uint32_t bRow = sb + BM * 64 + (uint32_t)(wn + rb) * 64;

    float acc[4][4][4];
#pragma unroll
    for (int i = 0; i < 4; i++)
#pragma unroll
        for (int j = 0; j < 4; j++)
#pragma unroll
            for (int k = 0; k < 4; k++) acc[i][j][k] = 0.f;

    LOAD_TILE(0, 0); CP_COMMIT();
    LOAD_TILE(1, 1); CP_COMMIT();
    LOAD_TILE(2, 2); CP_COMMIT();

    for (int kt = 0; kt < NTILES; kt++) {
        CP_WAIT2();
        __syncthreads();
        if (kt + 3 < NTILES) LOAD_TILE(kt + 3, (kt + 3) & 3);
        CP_COMMIT();

        uint32_t so = (uint32_t)(kt & 3) * STAGE_BYTES;
#pragma unroll
        for (int s16 = 0; s16 < 2; s16++) {
            uint32_t afr[4][4];
            uint32_t bfr[2][4];
            uint32_t ca = (uint32_t)(((2 * s16 + ahc) ^ xa) << 4);
            uint32_t cb = (uint32_t)(((2 * s16 + bhc) ^ xb) << 4);
#pragma unroll
            for (int mt = 0; mt < 4; mt++)
                ldsm4(afr[mt][0], afr[mt][1], afr[mt][2], afr[mt][3],
                      aRow + so + (uint32_t)mt * 1024 + ca);
#pragma unroll
            for (int nb = 0; nb < 2; nb++)
                ldsm4(bfr[nb][0], bfr[nb][1], bfr[nb][2], bfr[nb][3],
                      bRow + so + (uint32_t)nb * 1024 + cb);
#pragma unroll
            for (int mt = 0; mt < 4; mt++)
#pragma unroll
                for (int nt = 0; nt < 4; nt++) {
                    uint32_t bpair[2] = { bfr[nt >> 1][(nt & 1) * 2],
                                          bfr[nt >> 1][(nt & 1) * 2 + 1] };
                    mma_f16(acc[mt][nt], afr[mt], bpair);
                }
        }
    }

    // ---- epilogue ----
    int g = lane >> 2, t = lane & 3;

    // prior-activation bases for dot accumulation (a_0 = x, a_j = out col j-1)
    const float* ajb[3];
    int ajs[3];
    ajb[0] = x;            ajs[0] = D;
    ajb[1] = out_base;     ajs[1] = OUTD;
    ajb[2] = out_base + D; ajs[2] = OUTD;

#pragma unroll
    for (int mt = 0; mt < 4; mt++) {
        int mloc = wm + mt * 16 + g;
        int m0 = rowB + mloc;
        float c0 = c_s[mloc];
        float c1 = c_s[mloc + 8];
        float* o0 = out + (size_t)m0 * OUTD + colB;
        float* o1 = o0 + (size_t)8 * OUTD;
        __half* h0 = Oh + (size_t)m0 * D + colB;
        __half* h1 = h0 + (size_t)8 * D;

        const float* p0[3];
#pragma unroll
        for (int j = 0; j < 3; j++)
            p0[j] = ajb[j] + (size_t)m0 * ajs[j] + colB;

        float dac0[4] = {0.f, 0.f, 0.f, 0.f};
        float dac1[4] = {0.f, 0.f, 0.f, 0.f};

#pragma unroll
        for (int nt = 0; nt < 4; nt++) {
            int col = wn + nt * 8 + 2 * t;
            float w0 = wsum_s[col], w1 = wsum_s[col + 1];
            float bb0 = bias_s[col], bb1 = bias_s[col + 1];
            float v00 = acc[mt][nt][0] + c0 * w0 + bb0;
            float v01 = acc[mt][nt][1] + c0 * w1 + bb1;
            float v10 = acc[mt][nt][2] + c1 * w0 + bb0;
            float v11 = acc[mt][nt][3] + c1 * w1 + bb1;
            *(float2*)(o0 + col) = make_float2(v00, v01);
            *(float2*)(o1 + col) = make_float2(v10, v11);
            if (write_ah) {
                *(__half2*)(h0 + col) = __floats2half2_rn(v00, v01);
                *(__half2*)(h1 + col) = __floats2half2_rn(v10, v11);
            }
#pragma unroll
            for (int j = 0; j < 3; j++)
                if (j < ndots) {
                    float2 u0 = *(const float2*)(p0[j] + col);
                    float2 u1 = *(const float2*)(p0[j] + (size_t)8 * ajs[j] + col);
                    dac0[j] += v00 * u0.x + v01 * u0.y;
                    dac1[j] += v10 * u1.x + v11 * u1.y;
                }
            if (dosum) {
                dac0[3] += v00 + v01;
                dac1[3] += v10 + v11;
            }
        }

        // reduce across the 4 t-lanes (same g => same rows), then atomic
#pragma unroll
        for (int j = 0; j < 4; j++) {
            bool live = (j < ndots) || (j == 3 && dosum);
            if (!live) continue;
            float r0 = dac0[j], r1 = dac1[j];
            r0 += __shfl_xor_sync(0xffffffffu, r0, 1);
            r0 += __shfl_xor_sync(0xffffffffu, r0, 2);
            r1 += __shfl_xor_sync(0xffffffffu, r1, 1);
            r1 += __shfl_xor_sync(0xffffffffu, r1, 2);
            if (t == 0) {
                if (j < 3) {
                    atomicAdd(&g_dot[layer][j][m0], r0);
                    atomicAdd(&g_dot[layer][j][m0 + 8], r1);
                } else {
                    atomicAdd(&g_sum[layer + 1][m0], r0);
                    atomicAdd(&g_sum[layer + 1][m0 + 8], r1);
                }
            }
        }
    }
}

// ---------------------------------------------------------------------------
extern "C" void kernel_launch(void* const* d_in, const int* in_sizes, int n_in,
                              void* d_out, int out_size) {
    const float* x = (const float*)d_in[0];
    const float* W = (const float*)d_in[1];
    const float* b = (const float*)d_in[2];
    float* out = (float*)d_out;

    cudaFuncSetAttribute(gemm_h, cudaFuncAttributeMaxDynamicSharedMemorySize, SMEM_TOTAL);

    zero_aux<<<(9 * BATCH) / 256, 256>>>();
    prep_w<<<NLAYER * D / 8, 256>>>(W);
    conv_x<<<BATCH * 32 / 256, 256>>>(x);

    dim3 ggrid(D / BN, BATCH / BM);   // (4, 128)

    for (int i = 0; i < NLAYER; i++)
        gemm_h<<<ggrid, 256, SMEM_TOTAL>>>(i, i & 1, (i < NLAYER - 1) ? 1 : 0,
                                           x, b, out);
}

// round 6
// speedup vs baseline: 2.2803x; 1.1579x over previous
#include <cuda_runtime.h>
#include <cuda_fp16.h>
#include <cstdint>

#define BATCH  16384
#define D      512
#define OUTD   2048
#define NLAYER 4

#define BM 128
#define BN 128
#define NTILES 16
#define NROWB (BATCH / BM)                // 128
#define NITEMS (NLAYER * NROWB * 4)       // 2048
#define STAGE_BYTES (BM * 64 + BN * 64)   // 16384
#define SMEM_MAIN (4 * STAGE_BYTES)       // 65536
#define SMEM_TOTAL (SMEM_MAIN + 1536)

__device__ float  g_wsum[NLAYER * D];
__device__ float  g_dot[3][3][BATCH];
__device__ float  g_sum[3][BATCH];
__device__ unsigned g_ready[3][NROWB];
__device__ __half g_h0[(size_t)BATCH * D];
__device__ __half g_h1[(size_t)BATCH * D];
__device__ __half g_wh[(size_t)NLAYER * D * D];

// ---------------- helpers ----------------
__device__ __forceinline__ uint32_t s2u(const void* p) {
    uint32_t a;
    asm("{ .reg .u64 t; cvta.to.shared.u64 t, %1; cvt.u32.u64 %0, t; }" : "=r"(a) : "l"(p));
    return a;
}
__device__ __forceinline__ uint64_t g2g(const void* p) {
    uint64_t a;
    asm("cvta.to.global.u64 %0, %1;" : "=l"(a) : "l"(p));
    return a;
}
__device__ __forceinline__ void cp16(uint32_t s, uint64_t g) {
    asm volatile("cp.async.cg.shared.global [%0], [%1], 16;" :: "r"(s), "l"(g) : "memory");
}
#define CP_COMMIT() asm volatile("cp.async.commit_group;" ::: "memory")
#define CP_WAIT2()  asm volatile("cp.async.wait_group 2;" ::: "memory")

__device__ __forceinline__ void ldsm4(uint32_t& r0, uint32_t& r1, uint32_t& r2, uint32_t& r3,
                                      uint32_t addr) {
    asm volatile("ldmatrix.sync.aligned.m8n8.x4.shared.b16 {%0,%1,%2,%3}, [%4];"
                 : "=r"(r0), "=r"(r1), "=r"(r2), "=r"(r3) : "r"(addr));
}
__device__ __forceinline__ void mma_f16(float* c, const uint32_t* a, const uint32_t* b) {
    asm volatile(
        "mma.sync.aligned.m16n8k16.row.col.f32.f16.f16.f32 "
        "{%0,%1,%2,%3}, {%4,%5,%6,%7}, {%8,%9}, {%0,%1,%2,%3};\n"
        : "+f"(c[0]), "+f"(c[1]), "+f"(c[2]), "+f"(c[3])
        : "r"(a[0]), "r"(a[1]), "r"(a[2]), "r"(a[3]), "r"(b[0]), "r"(b[1]));
}

// ---------------- zero accumulators ----------------
__global__ void zero_aux() {
    int i = blockIdx.x * blockDim.x + threadIdx.x;
    if (i < 9 * BATCH) ((float*)g_dot)[i] = 0.f;
    if (i < 3 * BATCH) ((float*)g_sum)[i] = 0.f;
    if (i < 3 * NROWB) ((unsigned*)g_ready)[i] = 0u;
}

// ---------------- prep: W -> fp16 + wsum ----------------
__global__ void prep_w(const float* __restrict__ W) {
    int warp = (blockIdx.x * blockDim.x + threadIdx.x) >> 5;
    int lane = threadIdx.x & 31;
    if (warp >= NLAYER * D) return;
    const float4* row = (const float4*)(W + (size_t)warp * D);
    __half* hrow = g_wh + (size_t)warp * D;
    float s = 0.f;
#pragma unroll
    for (int k = 0; k < 4; k++) {
        int i4 = lane + 32 * k;
        float4 v = row[i4];
        s += v.x + v.y + v.z + v.w;
        __half2 h01 = __floats2half2_rn(v.x, v.y);
        __half2 h23 = __floats2half2_rn(v.z, v.w);
        uint2 pk = make_uint2(*(uint32_t*)&h01, *(uint32_t*)&h23);
        *(uint2*)(hrow + i4 * 4) = pk;
    }
#pragma unroll
    for (int off = 16; off; off >>= 1) s += __shfl_xor_sync(0xffffffffu, s, off);
    if (lane == 0) g_wsum[warp] = s;
}

// ---------------- prep: x -> fp16 + row sums ----------------
__global__ void conv_x(const float* __restrict__ x) {
    int row  = (blockIdx.x * blockDim.x + threadIdx.x) >> 5;
    int lane = threadIdx.x & 31;
    const float4* rp = (const float4*)(x + (size_t)row * D);
    __half* hp = g_h0 + (size_t)row * D;
    float s = 0.f;
#pragma unroll
    for (int k = 0; k < 4; k++) {
        int i4 = lane + 32 * k;
        float4 v = rp[i4];
        s += v.x + v.y + v.z + v.w;
        __half2 h01 = __floats2half2_rn(v.x, v.y);
        __half2 h23 = __floats2half2_rn(v.z, v.w);
        uint2 pk = make_uint2(*(uint32_t*)&h01, *(uint32_t*)&h23);
        *(uint2*)(hp + i4 * 4) = pk;
    }
#pragma unroll
    for (int off = 16; off; off >>= 1) s += __shfl_xor_sync(0xffffffffu, s, off);
    if (lane == 0) g_sum[0][row] = s;
}

// ---------------- persistent fused network ----------------
__global__ __launch_bounds__(256, 2)
void persist_net(const float* __restrict__ x,
                 const float* __restrict__ bias_all,
                 float* __restrict__ out_base)
{
    extern __shared__ __align__(128) char dsm[];
    uint32_t sb = s2u(dsm);
    float* wsum_s = (float*)(dsm + SMEM_MAIN);
    float* bias_s = (float*)(dsm + SMEM_MAIN + 512);
    float* c_s    = (float*)(dsm + SMEM_MAIN + 1024);

    int tid = threadIdx.x, warp = tid >> 5, lane = tid & 31;

    int wm = (warp >> 2) * 64;
    int wn = (warp & 3) * 32;
    int xa = ((lane & 15) >> 1) & 3;
    int rb = (lane & 7) + ((lane >> 4) << 3);
    int xb = (rb >> 1) & 3;
    int ahc = lane >> 4;
    int bhc = (lane >> 3) & 1;
    int u = tid & 3, r = tid >> 2;
    uint32_t swz = (uint32_t)((u ^ ((r >> 1) & 3)) << 4);
    uint32_t sA0 = sb + r * 64 + swz;
    uint32_t sB0 = sb + BM * 64 + r * 64 + swz;
    uint32_t aRow = sb + (uint32_t)(wm + (lane & 15)) * 64;
    uint32_t bRow = sb + BM * 64 + (uint32_t)(wn + rb) * 64;
    int g = lane >> 2, t = lane & 3;

    for (int item = blockIdx.x; item < NITEMS; item += gridDim.x) {
        int layer = item >> 9;
        int ti    = item & 511;
        int rowb  = ti >> 2;
        int col   = ti & 3;
        int rowB  = rowb * BM, colB = col * BN;
        int asel  = layer & 1;
        int write_ah = (layer < NLAYER - 1);
        int ndots = (layer < 3) ? (layer + 1) : 0;
        int dosum = (layer <= 1);

        const __half* Ah = asel ? g_h1 : g_h0;
        __half*       Oh = asel ? g_h0 : g_h1;
        const __half* Wl = g_wh + (size_t)layer * D * D;
        float* out = out_base + layer * D;

        uint64_t gA = g2g(Ah + (size_t)(rowB + r) * D + u * 8);
        uint64_t gB = g2g(Wl + (size_t)(colB + r) * D + u * 8);

#define LOAD_A(kt, st)                                                    \
        {                                                                 \
            uint32_t so = (uint32_t)(st) * STAGE_BYTES;                   \
            uint64_t go = (uint64_t)(kt) * 64;                            \
            cp16(sA0 + so,        gA + go);                               \
            cp16(sA0 + so + 4096, gA + go + 65536);                       \
        }
#define LOAD_B(kt, st)                                                    \
        {                                                                 \
            uint32_t so = (uint32_t)(st) * STAGE_BYTES;                   \
            uint64_t go = (uint64_t)(kt) * 64;                            \
            cp16(sB0 + so,        gB + go);                               \
            cp16(sB0 + so + 4096, gB + go + 65536);                       \
        }

        // prefetch B (weights, producer-independent) while we may spin
        LOAD_B(0, 0); LOAD_B(1, 1); LOAD_B(2, 2);

        if (layer > 0) {
            if (tid == 0) {
                const unsigned* cp = &g_ready[layer - 1][rowb];
                unsigned v;
                while (true) {
                    asm volatile("ld.acquire.gpu.global.u32 %0, [%1];"
                                 : "=r"(v) : "l"(cp) : "memory");
                    if (v >= 4u) break;
                    __nanosleep(64);
                }
            }
            __syncthreads();
        }

        if (tid < 128) {
            wsum_s[tid] = g_wsum[layer * D + colB + tid];
            bias_s[tid] = bias_all[layer * D + colB + tid];
            float c = 0.f;
            if (layer > 0) {
                int row = rowB + tid;
#pragma unroll
                for (int j = 0; j < 3; j++)
                    if (j < layer)
                        c = c + g_dot[layer - 1][j][row] + c * g_sum[j][row];
            }
            c_s[tid] = c;
        }

        LOAD_A(0, 0); CP_COMMIT();
        LOAD_A(1, 1); CP_COMMIT();
        LOAD_A(2, 2); CP_COMMIT();

        float acc[4][4][4];
#pragma unroll
        for (int i = 0; i < 4; i++)
#pragma unroll
            for (int j = 0; j < 4; j++)
#pragma unroll
                for (int k = 0; k < 4; k++) acc[i][j][k] = 0.f;

        for (int kt = 0; kt < NTILES; kt++) {
            CP_WAIT2();
            __syncthreads();
            if (kt + 3 < NTILES) { LOAD_A(kt + 3, (kt + 3) & 3); LOAD_B(kt + 3, (kt + 3) & 3); }
            CP_COMMIT();

            uint32_t so = (uint32_t)(kt & 3) * STAGE_BYTES;
#pragma unroll
            for (int s16 = 0; s16 < 2; s16++) {
                uint32_t afr[4][4];
                uint32_t bfr[2][4];
                uint32_t ca = (uint32_t)(((2 * s16 + ahc) ^ xa) << 4);
                uint32_t cb = (uint32_t)(((2 * s16 + bhc) ^ xb) << 4);
#pragma unroll
                for (int mt = 0; mt < 4; mt++)
                    ldsm4(afr[mt][0], afr[mt][1], afr[mt][2], afr[mt][3],
                          aRow + so + (uint32_t)mt * 1024 + ca);
#pragma unroll
                for (int nb = 0; nb < 2; nb++)
                    ldsm4(bfr[nb][0], bfr[nb][1], bfr[nb][2], bfr[nb][3],
                          bRow + so + (uint32_t)nb * 1024 + cb);
#pragma unroll
                for (int mt = 0; mt < 4; mt++)
#pragma unroll
                    for (int nt = 0; nt < 4; nt++) {
                        uint32_t bpair[2] = { bfr[nt >> 1][(nt & 1) * 2],
                                              bfr[nt >> 1][(nt & 1) * 2 + 1] };
                        mma_f16(acc[mt][nt], afr[mt], bpair);
                    }
            }
        }

        // ---- epilogue ----
        const float* ajb[3];
        int ajs[3];
        ajb[0] = x;            ajs[0] = D;
        ajb[1] = out_base;     ajs[1] = OUTD;
        ajb[2] = out_base + D; ajs[2] = OUTD;

#pragma unroll
        for (int mt = 0; mt < 4; mt++) {
            int mloc = wm + mt * 16 + g;
            int m0 = rowB + mloc;
            float c0 = c_s[mloc];
            float c1 = c_s[mloc + 8];
            float* o0 = out + (size_t)m0 * OUTD + colB;
            float* o1 = o0 + (size_t)8 * OUTD;
            __half* h0 = Oh + (size_t)m0 * D + colB;
            __half* h1 = h0 + (size_t)8 * D;

            const float* p0[3];
#pragma unroll
            for (int j = 0; j < 3; j++)
                p0[j] = ajb[j] + (size_t)m0 * ajs[j] + colB;

            float dac0[4] = {0.f, 0.f, 0.f, 0.f};
            float dac1[4] = {0.f, 0.f, 0.f, 0.f};

#pragma unroll
            for (int nt = 0; nt < 4; nt++) {
                int cc = wn + nt * 8 + 2 * t;
                float w0 = wsum_s[cc], w1 = wsum_s[cc + 1];
                float bb0 = bias_s[cc], bb1 = bias_s[cc + 1];
                float v00 = acc[mt][nt][0] + c0 * w0 + bb0;
                float v01 = acc[mt][nt][1] + c0 * w1 + bb1;
                float v10 = acc[mt][nt][2] + c1 * w0 + bb0;
                float v11 = acc[mt][nt][3] + c1 * w1 + bb1;
                *(float2*)(o0 + cc) = make_float2(v00, v01);
                *(float2*)(o1 + cc) = make_float2(v10, v11);
                if (write_ah) {
                    *(__half2*)(h0 + cc) = __floats2half2_rn(v00, v01);
                    *(__half2*)(h1 + cc) = __floats2half2_rn(v10, v11);
                }
#pragma unroll
                for (int j = 0; j < 3; j++)
                    if (j < ndots) {
                        float2 u0 = *(const float2*)(p0[j] + cc);
                        float2 u1 = *(const float2*)(p0[j] + (size_t)8 * ajs[j] + cc);
                        dac0[j] += v00 * u0.x + v01 * u0.y;
                        dac1[j] += v10 * u1.x + v11 * u1.y;
                    }
                if (dosum) {
                    dac0[3] += v00 + v01;
                    dac1[3] += v10 + v11;
                }
            }

#pragma unroll
            for (int j = 0; j < 4; j++) {
                bool live = (j < ndots) || (j == 3 && dosum);
                if (!live) continue;
                float r0 = dac0[j], r1 = dac1[j];
                r0 += __shfl_xor_sync(0xffffffffu, r0, 1);
                r0 += __shfl_xor_sync(0xffffffffu, r0, 2);
                r1 += __shfl_xor_sync(0xffffffffu, r1, 1);
                r1 += __shfl_xor_sync(0xffffffffu, r1, 2);
                if (t == 0) {
                    if (j < 3) {
                        atomicAdd(&g_dot[layer][j][m0], r0);
                        atomicAdd(&g_dot[layer][j][m0 + 8], r1);
                    } else {
                        atomicAdd(&g_sum[layer + 1][m0], r0);
                        atomicAdd(&g_sum[layer + 1][m0 + 8], r1);
                    }
                }
            }
        }

        // ---- signal completion ----
        __threadfence();
        __syncthreads();
        if (tid == 0 && layer < 3) {
            asm volatile("red.release.gpu.global.add.u32 [%0], %1;"
                         :: "l"(&g_ready[layer][rowb]), "r"(1u) : "memory");
        }
    }
}

// ---------------------------------------------------------------------------
extern "C" void kernel_launch(void* const* d_in, const int* in_sizes, int n_in,
                              void* d_out, int out_size) {
    const float* x = (const float*)d_in[0];
    const float* W = (const float*)d_in[1];
    const float* b = (const float*)d_in[2];
    float* out = (float*)d_out;

    cudaFuncSetAttribute(persist_net, cudaFuncAttributeMaxDynamicSharedMemorySize, SMEM_TOTAL);

    int dev = 0, sms = 148;
    cudaGetDevice(&dev);
    cudaDeviceGetAttribute(&sms, cudaDevAttrMultiProcessorCount, dev);
    int grid = 2 * sms;
    if (grid > NITEMS) grid = NITEMS;

    zero_aux<<<(9 * BATCH) / 256, 256>>>();
    prep_w<<<NLAYER * D / 8, 256>>>(W);
    conv_x<<<BATCH * 32 / 256, 256>>>(x);

    persist_net<<<grid, 256, SMEM_TOTAL>>>(x, b, out);
}